// round 4
// baseline (speedup 1.0000x reference)
#include <cuda_runtime.h>
#include <cstdint>

// ---------------------------------------------------------------------------
// MLSTMFixD: fractional-differencing mLSTM + LSTMCell stack + log_softmax head
// Shapes: T=128, B=256, I=512, H=512, K(lags)=32, O=5
// Strategy: per-step fused GEMM+epilogue kernels, packed fma.rn.f32x2 math,
//           circular hist buffer, ping-pong state buffers, all fp32.
// ---------------------------------------------------------------------------

typedef unsigned long long ull;

constexpr int T_   = 128;
constexpr int B_   = 256;
constexpr int I_   = 512;
constexpr int H_   = 512;
constexpr int O_   = 5;
constexpr int KLAG = 32;
constexpr int K1   = I_ + H_;   // 1024 (x | h1)
constexpr int K2   = H_ + H_;   // 1024 (h1n | h2)

// ------------------------- device scratch (static) -------------------------
__device__ float g_h1[2][B_ * H_];
__device__ float g_h2[2][B_ * H_];
__device__ float g_c2[2][B_ * H_];
__device__ float g_hist[KLAG][B_ * H_];   // circular: slot s holds c1 of latest step t with (t & 31)==s
__device__ float g_sel[B_ * H_];          // h2n gathered at t == length[b]
__device__ float g_wd[KLAG][H_];          // g_wd[j-1][h] = c_j (frac-diff coefficient for lag j)

// ------------------------------- helpers -----------------------------------
__device__ __forceinline__ void fma2(ull& acc, ull a, ull b) {
    // packed fp32x2 FMA (Blackwell FFMA2) — bit-identical to two scalar fmaf
    asm("fma.rn.f32x2 %0, %1, %2, %0;" : "+l"(acc) : "l"(a), "l"(b));
}
__device__ __forceinline__ float2 u2f2(ull v) {
    float2 r;
    asm("mov.b64 {%0, %1}, %2;" : "=f"(r.x), "=f"(r.y) : "l"(v));
    return r;
}
__device__ __forceinline__ float sigf(float x) { return 1.0f / (1.0f + expf(-x)); }

// ------------------------------- init --------------------------------------
__global__ __launch_bounds__(256) void init_kernel(const float* __restrict__ b_d) {
    const int tid    = blockIdx.x * blockDim.x + threadIdx.x;
    const int stride = gridDim.x * blockDim.x;

    float* hist_flat = &g_hist[0][0];
    for (int i = tid; i < KLAG * B_ * H_; i += stride) hist_flat[i] = 0.0f;
    for (int i = tid; i < B_ * H_; i += stride) {
        g_h1[0][i] = 0.0f;
        g_h2[0][i] = 0.0f;
        g_c2[0][i] = 0.0f;
        g_sel[i]   = 0.0f;
    }
    if (tid < H_) {
        // d = 0.5 * sigmoid(b_d[h]); c_j = prod_{i=0}^{j-1} (i - d)/(i + 1)
        float d = 0.5f * (1.0f / (1.0f + expf(-b_d[tid])));
        float c = 1.0f;
        for (int j = 1; j <= KLAG; j++) {
            c *= ((float)(j - 1) - d) / (float)j;
            g_wd[j - 1][tid] = c;
        }
    }
}

// --------------------- step kernel 1: mLSTM cell ----------------------------
// G = [x_t | h1] @ [W_mih | W_mhh]^T + b_mih + b_mhh   (256 x 1536)
// CTA tile: 32 rows (batch) x 32 h-cols across ALL 3 gates (96 cols), K=1024.
// Epilogue: gates -> frac filter over hist -> c1 -> hist slot + h1n.
__global__ __launch_bounds__(128) void step1_kernel(
    const float* __restrict__ x,
    const float* __restrict__ Wmih, const float* __restrict__ Wmhh,
    const float* __restrict__ bmih, const float* __restrict__ bmhh,
    int t)
{
    __shared__ __align__(16) float2 Ash[32][33];   // [kk][row], value duplicated {a,a}
    __shared__ __align__(16) float  Bsh[32][98];   // [kk][col 0..95], cols grouped by gate

    const int tid = threadIdx.x;
    const int tx  = tid & 15;    // column-pair index (cols 2tx, 2tx+1 per gate)
    const int ty  = tid >> 4;    // 0..7 (rows ty + 8*i)
    const int bm  = blockIdx.x * 32;
    const int hn  = blockIdx.y * 32;

    const float* __restrict__ h1  = g_h1[t & 1];
    float*       __restrict__ h1n = g_h1[(t + 1) & 1];
    const float* __restrict__ xt  = x + (size_t)t * (B_ * I_);

    ull acc[4][3];
#pragma unroll
    for (int i = 0; i < 4; i++)
#pragma unroll
        for (int g = 0; g < 3; g++) acc[i][g] = 0ULL;

    for (int k0 = 0; k0 < K1; k0 += 32) {
        const float* __restrict__ Abase = (k0 < I_) ? (xt + k0) : (h1 + (k0 - I_));
        const float* __restrict__ Wbase = (k0 < I_) ? (Wmih + k0) : (Wmhh + (k0 - I_));

        // A tile: 32 rows x 32 k = 256 float4 (2 per thread), duplicated into smem
#pragma unroll
        for (int r = 0; r < 2; r++) {
            int f4  = tid + r * 128;        // 0..255
            int row = f4 >> 3;              // 0..31
            int kq  = (f4 & 7) << 2;        // 0,4,...,28
            float4 v = *reinterpret_cast<const float4*>(Abase + (size_t)(bm + row) * 512 + kq);
            Ash[kq + 0][row] = make_float2(v.x, v.x);
            Ash[kq + 1][row] = make_float2(v.y, v.y);
            Ash[kq + 2][row] = make_float2(v.z, v.z);
            Ash[kq + 3][row] = make_float2(v.w, v.w);
        }
        // B tile: 96 cols x 32 k = 768 float4 (6 per thread)
#pragma unroll
        for (int r = 0; r < 6; r++) {
            int f4   = tid + r * 128;       // 0..767
            int col  = f4 >> 3;             // 0..95
            int kq   = (f4 & 7) << 2;
            int gate = col >> 5;
            int cc   = col & 31;
            int wrow = gate * H_ + hn + cc;
            float4 v = *reinterpret_cast<const float4*>(Wbase + (size_t)wrow * 512 + kq);
            Bsh[kq + 0][col] = v.x;
            Bsh[kq + 1][col] = v.y;
            Bsh[kq + 2][col] = v.z;
            Bsh[kq + 3][col] = v.w;
        }
        __syncthreads();

#pragma unroll
        for (int kk = 0; kk < 32; kk++) {
            const ull* __restrict__ arow = reinterpret_cast<const ull*>(&Ash[kk][0]);
            const ull* __restrict__ brow = reinterpret_cast<const ull*>(&Bsh[kk][0]);
            ull b0 = brow[tx];
            ull b1 = brow[16 + tx];
            ull b2 = brow[32 + tx];
#pragma unroll
            for (int i = 0; i < 4; i++) {
                ull a = arow[ty + 8 * i];
                fma2(acc[i][0], a, b0);
                fma2(acc[i][1], a, b1);
                fma2(acc[i][2], a, b2);
            }
        }
        __syncthreads();
    }

    // ---- epilogue: gates, fractional-differencing filter, hist update ----
    const int slot_w = t & (KLAG - 1);
#pragma unroll
    for (int i = 0; i < 4; i++) {
        const int b = bm + ty + 8 * i;
        float2 v0 = u2f2(acc[i][0]);
        float2 v1 = u2f2(acc[i][1]);
        float2 v2 = u2f2(acc[i][2]);
        float pi[2] = {v0.x, v0.y};
        float po[2] = {v1.x, v1.y};
        float pg[2] = {v2.x, v2.y};
#pragma unroll
        for (int c = 0; c < 2; c++) {
            const int hc  = hn + 2 * tx + c;
            const int idx = b * H_ + hc;
            float vi = sigf (pi[c] + bmih[hc]           + bmhh[hc]);
            float vo = sigf (po[c] + bmih[H_ + hc]      + bmhh[H_ + hc]);
            float vg = tanhf(pg[c] + bmih[2 * H_ + hc]  + bmhh[2 * H_ + hc]);
            // fs = sum_{j=1..K} c_j * c1_{t-j}; unwritten (future) slots are still 0
            float fs = 0.0f;
#pragma unroll
            for (int j = 1; j <= KLAG; j++)
                fs = fmaf(g_wd[j - 1][hc], g_hist[(t - j + KLAG) & (KLAG - 1)][idx], fs);
            float c1 = vi * vg - fs;
            g_hist[slot_w][idx] = c1;
            h1n[idx] = vo * tanhf(c1);
        }
    }
}

// --------------------- step kernel 2: LSTMCell ------------------------------
// G2 = [h1n | h2] @ [W_ih | W_hh]^T + b_ih + b_hh   (256 x 2048)
// CTA tile: 32 rows x 32 h-cols across ALL 4 gates (128 cols), K=1024.
__global__ __launch_bounds__(128) void step2_kernel(
    const float* __restrict__ Wih, const float* __restrict__ Whh,
    const float* __restrict__ bih, const float* __restrict__ bhh,
    const int*   __restrict__ length,
    int t)
{
    __shared__ __align__(16) float2 Ash[32][33];
    __shared__ __align__(16) float  Bsh[32][130];  // 128 cols + pad 2

    const int tid = threadIdx.x;
    const int tx  = tid & 15;
    const int ty  = tid >> 4;
    const int bm  = blockIdx.x * 32;
    const int hn  = blockIdx.y * 32;

    const float* __restrict__ h1n = g_h1[(t + 1) & 1];
    const float* __restrict__ h2  = g_h2[t & 1];
    const float* __restrict__ c2p = g_c2[t & 1];
    float*       __restrict__ h2n = g_h2[(t + 1) & 1];
    float*       __restrict__ c2n = g_c2[(t + 1) & 1];

    ull acc[4][4];
#pragma unroll
    for (int i = 0; i < 4; i++)
#pragma unroll
        for (int g = 0; g < 4; g++) acc[i][g] = 0ULL;

    for (int k0 = 0; k0 < K2; k0 += 32) {
        const float* __restrict__ Abase = (k0 < H_) ? (h1n + k0) : (h2 + (k0 - H_));
        const float* __restrict__ Wbase = (k0 < H_) ? (Wih + k0) : (Whh + (k0 - H_));

#pragma unroll
        for (int r = 0; r < 2; r++) {
            int f4  = tid + r * 128;
            int row = f4 >> 3;
            int kq  = (f4 & 7) << 2;
            float4 v = *reinterpret_cast<const float4*>(Abase + (size_t)(bm + row) * 512 + kq);
            Ash[kq + 0][row] = make_float2(v.x, v.x);
            Ash[kq + 1][row] = make_float2(v.y, v.y);
            Ash[kq + 2][row] = make_float2(v.z, v.z);
            Ash[kq + 3][row] = make_float2(v.w, v.w);
        }
        // B tile: 128 cols x 32 k = 1024 float4 (8 per thread)
#pragma unroll
        for (int r = 0; r < 8; r++) {
            int f4   = tid + r * 128;       // 0..1023
            int col  = f4 >> 3;             // 0..127
            int kq   = (f4 & 7) << 2;
            int gate = col >> 5;
            int cc   = col & 31;
            int wrow = gate * H_ + hn + cc;
            float4 v = *reinterpret_cast<const float4*>(Wbase + (size_t)wrow * 512 + kq);
            Bsh[kq + 0][col] = v.x;
            Bsh[kq + 1][col] = v.y;
            Bsh[kq + 2][col] = v.z;
            Bsh[kq + 3][col] = v.w;
        }
        __syncthreads();

#pragma unroll
        for (int kk = 0; kk < 32; kk++) {
            const ull* __restrict__ arow = reinterpret_cast<const ull*>(&Ash[kk][0]);
            const ull* __restrict__ brow = reinterpret_cast<const ull*>(&Bsh[kk][0]);
            ull b0 = brow[tx];
            ull b1 = brow[16 + tx];
            ull b2 = brow[32 + tx];
            ull b3 = brow[48 + tx];
#pragma unroll
            for (int i = 0; i < 4; i++) {
                ull a = arow[ty + 8 * i];
                fma2(acc[i][0], a, b0);
                fma2(acc[i][1], a, b1);
                fma2(acc[i][2], a, b2);
                fma2(acc[i][3], a, b3);
            }
        }
        __syncthreads();
    }

    // ---- epilogue: LSTM cell update + output gather ----
#pragma unroll
    for (int i = 0; i < 4; i++) {
        const int b    = bm + ty + 8 * i;
        const int lenb = length[b];
        float2 v0 = u2f2(acc[i][0]);
        float2 v1 = u2f2(acc[i][1]);
        float2 v2 = u2f2(acc[i][2]);
        float2 v3 = u2f2(acc[i][3]);
        float p0[2] = {v0.x, v0.y};
        float p1[2] = {v1.x, v1.y};
        float p2[2] = {v2.x, v2.y};
        float p3[2] = {v3.x, v3.y};
#pragma unroll
        for (int c = 0; c < 2; c++) {
            const int hc  = hn + 2 * tx + c;
            const int idx = b * H_ + hc;
            float xi = sigf (p0[c] + bih[hc]          + bhh[hc]);
            float xf = sigf (p1[c] + bih[H_ + hc]     + bhh[H_ + hc]);
            float xg = tanhf(p2[c] + bih[2 * H_ + hc] + bhh[2 * H_ + hc]);
            float xo = sigf (p3[c] + bih[3 * H_ + hc] + bhh[3 * H_ + hc]);
            float cn = xf * c2p[idx] + xi * xg;
            c2n[idx] = cn;
            float hv = tanhf(xo * tanhf(cn));
            h2n[idx] = hv;
            if (lenb == t) g_sel[idx] = hv;
        }
    }
}

// ------------------------------- head ---------------------------------------
// logits = sel @ W_out^T + b_out; out = log_softmax(logits). One warp per b.
__global__ __launch_bounds__(128) void head_kernel(
    const float* __restrict__ Wout, const float* __restrict__ bout,
    float* __restrict__ out)
{
    const int warp = (blockIdx.x * blockDim.x + threadIdx.x) >> 5;
    const int lane = threadIdx.x & 31;
    if (warp >= B_) return;

    float p[O_] = {0.f, 0.f, 0.f, 0.f, 0.f};
    for (int h = lane; h < H_; h += 32) {
        float s = g_sel[warp * H_ + h];
#pragma unroll
        for (int o = 0; o < O_; o++) p[o] = fmaf(s, Wout[o * H_ + h], p[o]);
    }
#pragma unroll
    for (int o = 0; o < O_; o++)
#pragma unroll
        for (int off = 16; off > 0; off >>= 1)
            p[o] += __shfl_xor_sync(0xffffffffu, p[o], off);

    if (lane == 0) {
        float l[O_], m = -1e30f;
#pragma unroll
        for (int o = 0; o < O_; o++) { l[o] = p[o] + bout[o]; m = fmaxf(m, l[o]); }
        float s = 0.0f;
#pragma unroll
        for (int o = 0; o < O_; o++) s += expf(l[o] - m);
        float ls = logf(s);
#pragma unroll
        for (int o = 0; o < O_; o++) out[warp * O_ + o] = l[o] - m - ls;
    }
}

// ----------------------------- launcher -------------------------------------
extern "C" void kernel_launch(void* const* d_in, const int* in_sizes, int n_in,
                              void* d_out, int out_size)
{
    const float* x    = (const float*)d_in[0];   // (T,B,I)
    const int*   len  = (const int*)  d_in[1];   // (B,)
    const float* b_d  = (const float*)d_in[2];   // (1,H)
    const float* Wmih = (const float*)d_in[3];   // (3H,I)
    const float* Wmhh = (const float*)d_in[4];   // (3H,H)
    const float* bmih = (const float*)d_in[5];   // (3H,)
    const float* bmhh = (const float*)d_in[6];   // (3H,)
    const float* Wih  = (const float*)d_in[7];   // (4H,H)
    const float* Whh  = (const float*)d_in[8];   // (4H,H)
    const float* bih  = (const float*)d_in[9];   // (4H,)
    const float* bhh  = (const float*)d_in[10];  // (4H,)
    const float* Wout = (const float*)d_in[11];  // (O,H)
    const float* bout = (const float*)d_in[12];  // (O,)
    float* out = (float*)d_out;                  // (B,O)

    init_kernel<<<1024, 256>>>(b_d);

    dim3 grid(B_ / 32, H_ / 32);   // 8 x 16 = 128 CTAs
    for (int t = 0; t < T_; t++) {
        step1_kernel<<<grid, 128>>>(x, Wmih, Wmhh, bmih, bmhh, t);
        step2_kernel<<<grid, 128>>>(Wih, Whh, bih, bhh, len, t);
    }

    head_kernel<<<64, 128>>>(Wout, bout, out);
}

// round 6
// speedup vs baseline: 3.2934x; 3.2934x over previous
#include <cuda_runtime.h>
#include <cuda_bf16.h>
#include <cstdint>

typedef uint32_t u32;
typedef uint64_t u64;
typedef unsigned short u16;

// ---------------------------------------------------------------------------
// MLSTMFixD via legacy-path tensor cores (mma.sync bf16, 3-term split, fp32 acc)
// T=128, B=256, I=512, H=512, K(lags)=32, O=5
// No sm_103a-only features: mma.sync / ldmatrix / cp.async only.
// ---------------------------------------------------------------------------

constexpr int T_   = 128;
constexpr int B_   = 256;
constexpr int I_   = 512;
constexpr int H_   = 512;
constexpr int O_   = 5;
constexpr int KLAG = 32;
constexpr int BH   = B_ * H_;
constexpr int N1   = 3 * H_;   // 1536
constexpr int N2   = 4 * H_;   // 2048
constexpr int KTOT = 1024;
constexpr int NKC  = 16;       // K chunks of 64

// smem: 2 buffers x (Ahi|Alo|Bhi|Blo, 8KB each) = 64KB
constexpr int SMEM_BYTES = 2 * 32768;

// ------------------------- device scratch (static) -------------------------
__device__ __align__(16) u16 g_xhi[T_ * B_ * I_];     // pre-split x, bf16 hi
__device__ __align__(16) u16 g_xlo[T_ * B_ * I_];     // bf16 lo (residual)
__device__ __align__(16) u16 g_WmHi[N1 * KTOT], g_WmLo[N1 * KTOT];  // [Wmih|Wmhh]
__device__ __align__(16) u16 g_W2Hi[N2 * KTOT], g_W2Lo[N2 * KTOT];  // [Wih|Whh]
__device__ __align__(16) u16 g_h1hi[BH], g_h1lo[BH];
__device__ __align__(16) u16 g_h2hi[BH], g_h2lo[BH];
__device__ float g_c2[BH];
__device__ float g_sel[BH];
__device__ float g_hist[KLAG][BH];   // circular by (t & 31)
__device__ float g_wd[KLAG][H_];
__device__ float g_G1[B_ * N1];
__device__ float g_G2[B_ * N2];

// ------------------------------- helpers ------------------------------------
__device__ __forceinline__ u32 smem_u32(const void* p) {
    u32 a;
    asm("{ .reg .u64 t; cvta.to.shared.u64 t, %1; cvt.u32.u64 %0, t; }" : "=r"(a) : "l"(p));
    return a;
}
__device__ __forceinline__ void cpasync16(u32 dst, const void* src) {
    asm volatile("cp.async.cg.shared.global [%0], [%1], 16;" :: "r"(dst), "l"(src));
}
#define CP_COMMIT() asm volatile("cp.async.commit_group;" ::: "memory")
#define CP_WAIT(n)  asm volatile("cp.async.wait_group %0;" :: "n"(n) : "memory")

#define LDSM4(r, addr) asm volatile(                                           \
    "ldmatrix.sync.aligned.m8n8.x4.shared.b16 {%0,%1,%2,%3}, [%4];"            \
    : "=r"((r)[0]), "=r"((r)[1]), "=r"((r)[2]), "=r"((r)[3]) : "r"(addr))

#define MMA(d, a, b0, b1) asm volatile(                                        \
    "mma.sync.aligned.m16n8k16.row.col.f32.bf16.bf16.f32 "                     \
    "{%0,%1,%2,%3}, {%4,%5,%6,%7}, {%8,%9}, {%0,%1,%2,%3};"                    \
    : "+f"((d)[0]), "+f"((d)[1]), "+f"((d)[2]), "+f"((d)[3])                   \
    : "r"((a)[0]), "r"((a)[1]), "r"((a)[2]), "r"((a)[3]), "r"(b0), "r"(b1))

__device__ __forceinline__ u16 bf16bits(__nv_bfloat16 v) {
    __nv_bfloat16_raw r = *reinterpret_cast<__nv_bfloat16_raw*>(&v);
    return r.x;
}
// split: a = hi + lo (both bf16); residual captures ~18 bits of mantissa total
__device__ __forceinline__ void split1(float a, u16& h, u16& l) {
    __nv_bfloat16 bh = __float2bfloat16_rn(a);
    float r = a - __bfloat162float(bh);
    __nv_bfloat16 bl = __float2bfloat16_rn(r);
    h = bf16bits(bh);
    l = bf16bits(bl);
}
__device__ __forceinline__ void split4(float4 v, u32& h01, u32& h23, u32& l01, u32& l23) {
    u16 h0, l0, h1, l1, h2, l2, h3, l3;
    split1(v.x, h0, l0); split1(v.y, h1, l1);
    split1(v.z, h2, l2); split1(v.w, h3, l3);
    h01 = (u32)h0 | ((u32)h1 << 16);  h23 = (u32)h2 | ((u32)h3 << 16);
    l01 = (u32)l0 | ((u32)l1 << 16);  l23 = (u32)l2 | ((u32)l3 << 16);
}
__device__ __forceinline__ float sigf(float x) { return 1.0f / (1.0f + expf(-x)); }

// ------------------------------- init ---------------------------------------
__global__ __launch_bounds__(256) void init_kernel(
    const float* __restrict__ b_d,  const float* __restrict__ x,
    const float* __restrict__ Wmih, const float* __restrict__ Wmhh,
    const float* __restrict__ Wih,  const float* __restrict__ Whh)
{
    const int tid = blockIdx.x * blockDim.x + threadIdx.x;
    const int tot = gridDim.x * blockDim.x;

    // ---- x split (groups of 4 floats) ----
    const int ngx = T_ * B_ * I_ / 4;
    for (int i = tid; i < ngx; i += tot) {
        float4 v = reinterpret_cast<const float4*>(x)[i];
        u32 h01, h23, l01, l23;
        split4(v, h01, h23, l01, l23);
        reinterpret_cast<uint2*>(g_xhi)[i] = make_uint2(h01, h23);
        reinterpret_cast<uint2*>(g_xlo)[i] = make_uint2(l01, l23);
    }

    // ---- weight split into [N][1024] panels (cols 0-511 ih, 512-1023 hh) ----
    const int ngw = (N1 + N2) * KTOT / 4;
    for (int i = tid; i < ngw; i += tot) {
        int e = i * 4;
        const float* src;
        u16 *Hi, *Lo;
        int off;
        if (e < N1 * KTOT) {
            int n = e >> 10, k = e & 1023;
            src = (k < 512) ? (Wmih + (size_t)n * 512 + k) : (Wmhh + (size_t)n * 512 + (k - 512));
            Hi = g_WmHi; Lo = g_WmLo; off = e;
        } else {
            int e2 = e - N1 * KTOT;
            int n = e2 >> 10, k = e2 & 1023;
            src = (k < 512) ? (Wih + (size_t)n * 512 + k) : (Whh + (size_t)n * 512 + (k - 512));
            Hi = g_W2Hi; Lo = g_W2Lo; off = e2;
        }
        float4 v = *reinterpret_cast<const float4*>(src);
        u32 h01, h23, l01, l23;
        split4(v, h01, h23, l01, l23);
        reinterpret_cast<uint2*>(Hi)[off >> 2] = make_uint2(h01, h23);
        reinterpret_cast<uint2*>(Lo)[off >> 2] = make_uint2(l01, l23);
    }

    // ---- zero state ----
    float4 z4 = make_float4(0.f, 0.f, 0.f, 0.f);
    for (int i = tid; i < KLAG * BH / 4; i += tot)
        reinterpret_cast<float4*>(&g_hist[0][0])[i] = z4;
    for (int i = tid; i < BH / 4; i += tot) {
        reinterpret_cast<float4*>(g_c2)[i]  = z4;
        reinterpret_cast<float4*>(g_sel)[i] = z4;
        reinterpret_cast<uint2*>(g_h1hi)[i] = make_uint2(0u, 0u);
        reinterpret_cast<uint2*>(g_h1lo)[i] = make_uint2(0u, 0u);
        reinterpret_cast<uint2*>(g_h2hi)[i] = make_uint2(0u, 0u);
        reinterpret_cast<uint2*>(g_h2lo)[i] = make_uint2(0u, 0u);
    }

    // ---- frac-diff coefficients ----
    if (tid < H_) {
        float d = 0.5f * (1.0f / (1.0f + expf(-b_d[tid])));
        float c = 1.0f;
        for (int j = 1; j <= KLAG; j++) {
            c *= ((float)(j - 1) - d) / (float)j;
            g_wd[j - 1][tid] = c;
        }
    }
}

// ------------------------------- GEMM ---------------------------------------
// SET=0: G1[256,1536] = [x_t | h1] @ Wm^T     grid (24, 4)
// SET=1: G2[256,2048] = [h1n | h2] @ W2^T     grid (32, 4)
// CTA 64x64 tile, 256 thr (8 warps 2x4, warp tile 32x16), K in 16 chunks of 64,
// cp.async double-buffered, swizzled smem, ldmatrix fragments, 3 mma per term set.
template <int SET>
__global__ __launch_bounds__(256) void gemm_kernel(int t)
{
    extern __shared__ __align__(128) char smem[];
    const u32 sb  = smem_u32(smem);
    const int tid = threadIdx.x;
    const int wid = tid >> 5, lane = tid & 31;
    const int bn  = blockIdx.x * 64;
    const int bm  = blockIdx.y * 64;

    const u16* __restrict__ A0hi = SET ? g_h1hi : (g_xhi + (size_t)t * (B_ * I_));
    const u16* __restrict__ A0lo = SET ? g_h1lo : (g_xlo + (size_t)t * (B_ * I_));
    const u16* __restrict__ A1hi = SET ? g_h2hi : g_h1hi;
    const u16* __restrict__ A1lo = SET ? g_h2lo : g_h1lo;
    const u16* __restrict__ WHi  = SET ? g_W2Hi : g_WmHi;
    const u16* __restrict__ WLo  = SET ? g_W2Lo : g_WmLo;
    float*     __restrict__ G    = SET ? g_G2   : g_G1;
    const int ldG = SET ? N2 : N1;

    // loader: per chunk, each thread moves 8x 16B units (2 per 8KB tile)
    const int lr  = tid >> 3;          // unit row for j=0 (0..31)
    const int lcu = tid & 7;           // unit col 0..7
    auto load_chunk = [&](int c, int buf) {
        const int k0 = c * 64;
        const u16* ah;
        const u16* al;
        if (k0 < 512) { ah = A0hi + k0;         al = A0lo + k0;         }
        else          { ah = A1hi + (k0 - 512); al = A1lo + (k0 - 512); }
        const u32 base = sb + buf * 32768;
#pragma unroll
        for (int j = 0; j < 2; j++) {
            const int r = lr + j * 32;
            const u32 so = (u32)(r * 128 + ((lcu ^ (r & 7)) << 4));
            const size_t ao = (size_t)(bm + r) * 512 + lcu * 8;
            const size_t bo = (size_t)(bn + r) * 1024 + k0 + lcu * 8;
            cpasync16(base + so,         ah  + ao);
            cpasync16(base + 8192 + so,  al  + ao);
            cpasync16(base + 16384 + so, WHi + bo);
            cpasync16(base + 24576 + so, WLo + bo);
        }
    };

    // fragment addressing (precompute row-dependent parts)
    const int warp_m = wid & 1;        // 0..1 -> m offset 32*warp_m
    const int warp_n = wid >> 1;       // 0..3 -> n offset 16*warp_n
    const int arow   = warp_m * 32 + (lane & 15);
    const int akh    = lane >> 4;                                  // A k-half
    const int brow   = warp_n * 16 + (lane & 7) + ((lane >> 4) << 3);
    const int bkh    = (lane >> 3) & 1;                            // B k-half
    const u32 aoff0  = (u32)(arow * 128);
    const u32 aoff1  = (u32)((arow + 16) * 128);
    const int asw    = arow & 7;       // (arow+16)&7 == asw
    const u32 boff   = (u32)(brow * 128);
    const int bsw    = brow & 7;

    float acc[2][2][4] = {};

    load_chunk(0, 0);
    CP_COMMIT();

    for (int c = 0; c < NKC; c++) {
        if (c + 1 < NKC) {
            load_chunk(c + 1, (c + 1) & 1);
            CP_COMMIT();
            CP_WAIT(1);
        } else {
            CP_WAIT(0);
        }
        __syncthreads();

        const u32 Ah = sb + (c & 1) * 32768;
        const u32 Al = Ah + 8192;
        const u32 Bh = Ah + 16384;
        const u32 Bl = Ah + 24576;

#pragma unroll
        for (int kk = 0; kk < 4; kk++) {
            const u32 ca = (u32)(kk * 2 + akh);
            const u32 sa = ((ca ^ (u32)asw) << 4);
            const u32 cb = (u32)(kk * 2 + bkh);
            const u32 sbo = ((cb ^ (u32)bsw) << 4);

            u32 ah0[4], ah1[4], al0[4], al1[4], bh[4], bl[4];
            LDSM4(ah0, Ah + aoff0 + sa);
            LDSM4(ah1, Ah + aoff1 + sa);
            LDSM4(al0, Al + aoff0 + sa);
            LDSM4(al1, Al + aoff1 + sa);
            LDSM4(bh,  Bh + boff + sbo);
            LDSM4(bl,  Bl + boff + sbo);

#pragma unroll
            for (int nt = 0; nt < 2; nt++) {
                MMA(acc[0][nt], ah0, bh[2 * nt], bh[2 * nt + 1]);
                MMA(acc[1][nt], ah1, bh[2 * nt], bh[2 * nt + 1]);
                MMA(acc[0][nt], ah0, bl[2 * nt], bl[2 * nt + 1]);
                MMA(acc[1][nt], ah1, bl[2 * nt], bl[2 * nt + 1]);
                MMA(acc[0][nt], al0, bh[2 * nt], bh[2 * nt + 1]);
                MMA(acc[1][nt], al1, bh[2 * nt], bh[2 * nt + 1]);
            }
        }
        __syncthreads();
    }

    // ---- epilogue: fp32 accumulators -> G ----
#pragma unroll
    for (int mt = 0; mt < 2; mt++) {
#pragma unroll
        for (int nt = 0; nt < 2; nt++) {
            const int gm = bm + warp_m * 32 + mt * 16 + (lane >> 2);
            const int gn = bn + warp_n * 16 + nt * 8 + 2 * (lane & 3);
            *reinterpret_cast<float2*>(&G[(size_t)gm * ldG + gn]) =
                make_float2(acc[mt][nt][0], acc[mt][nt][1]);
            *reinterpret_cast<float2*>(&G[(size_t)(gm + 8) * ldG + gn]) =
                make_float2(acc[mt][nt][2], acc[mt][nt][3]);
        }
    }
}

// --------------------- epilogue 1: mLSTM gates + frac filter -----------------
__global__ __launch_bounds__(256) void epi1_kernel(
    const float* __restrict__ bmih, const float* __restrict__ bmhh, int t)
{
    const int idx = blockIdx.x * blockDim.x + threadIdx.x;
    const int b = idx >> 9, hc = idx & 511;
    const float* __restrict__ Gr = g_G1 + (size_t)b * N1;

    float vi = sigf (Gr[hc]        + bmih[hc]        + bmhh[hc]);
    float vo = sigf (Gr[512 + hc]  + bmih[512 + hc]  + bmhh[512 + hc]);
    float vg = tanhf(Gr[1024 + hc] + bmih[1024 + hc] + bmhh[1024 + hc]);

    float fs = 0.0f;
#pragma unroll
    for (int j = 1; j <= KLAG; j++)
        fs = fmaf(g_wd[j - 1][hc], g_hist[(t - j) & (KLAG - 1)][idx], fs);

    float c1 = vi * vg - fs;
    g_hist[t & (KLAG - 1)][idx] = c1;
    float h1n = vo * tanhf(c1);
    split1(h1n, g_h1hi[idx], g_h1lo[idx]);
}

// --------------------- epilogue 2: LSTM cell + gather ------------------------
__global__ __launch_bounds__(256) void epi2_kernel(
    const float* __restrict__ bih, const float* __restrict__ bhh,
    const int* __restrict__ length, int t)
{
    const int idx = blockIdx.x * blockDim.x + threadIdx.x;
    const int b = idx >> 9, hc = idx & 511;
    const float* __restrict__ Gr = g_G2 + (size_t)b * N2;

    float xi = sigf (Gr[hc]        + bih[hc]        + bhh[hc]);
    float xf = sigf (Gr[512 + hc]  + bih[512 + hc]  + bhh[512 + hc]);
    float xg = tanhf(Gr[1024 + hc] + bih[1024 + hc] + bhh[1024 + hc]);
    float xo = sigf (Gr[1536 + hc] + bih[1536 + hc] + bhh[1536 + hc]);

    float cn = xf * g_c2[idx] + xi * xg;
    g_c2[idx] = cn;
    float hv = tanhf(xo * tanhf(cn));
    split1(hv, g_h2hi[idx], g_h2lo[idx]);
    if (length[b] == t) g_sel[idx] = hv;
}

// ------------------------------- head ---------------------------------------
__global__ __launch_bounds__(128) void head_kernel(
    const float* __restrict__ Wout, const float* __restrict__ bout,
    float* __restrict__ out)
{
    const int warp = (blockIdx.x * blockDim.x + threadIdx.x) >> 5;
    const int lane = threadIdx.x & 31;
    if (warp >= B_) return;

    float p[O_] = {0.f, 0.f, 0.f, 0.f, 0.f};
    for (int h = lane; h < H_; h += 32) {
        float s = g_sel[warp * H_ + h];
#pragma unroll
        for (int o = 0; o < O_; o++) p[o] = fmaf(s, Wout[o * H_ + h], p[o]);
    }
#pragma unroll
    for (int o = 0; o < O_; o++)
#pragma unroll
        for (int off = 16; off > 0; off >>= 1)
            p[o] += __shfl_xor_sync(0xffffffffu, p[o], off);

    if (lane == 0) {
        float l[O_], m = -1e30f;
#pragma unroll
        for (int o = 0; o < O_; o++) { l[o] = p[o] + bout[o]; m = fmaxf(m, l[o]); }
        float s = 0.0f;
#pragma unroll
        for (int o = 0; o < O_; o++) s += expf(l[o] - m);
        float ls = logf(s);
#pragma unroll
        for (int o = 0; o < O_; o++) out[warp * O_ + o] = l[o] - m - ls;
    }
}

// ----------------------------- launcher -------------------------------------
extern "C" void kernel_launch(void* const* d_in, const int* in_sizes, int n_in,
                              void* d_out, int out_size)
{
    const float* x    = (const float*)d_in[0];   // (T,B,I)
    const int*   len  = (const int*)  d_in[1];   // (B,)
    const float* b_d  = (const float*)d_in[2];   // (1,H)
    const float* Wmih = (const float*)d_in[3];   // (3H,I)
    const float* Wmhh = (const float*)d_in[4];   // (3H,H)
    const float* bmih = (const float*)d_in[5];   // (3H,)
    const float* bmhh = (const float*)d_in[6];   // (3H,)
    const float* Wih  = (const float*)d_in[7];   // (4H,H)
    const float* Whh  = (const float*)d_in[8];   // (4H,H)
    const float* bih  = (const float*)d_in[9];   // (4H,)
    const float* bhh  = (const float*)d_in[10];  // (4H,)
    const float* Wout = (const float*)d_in[11];  // (O,H)
    const float* bout = (const float*)d_in[12];  // (O,)
    float* out = (float*)d_out;                  // (B,O)

    cudaFuncSetAttribute(gemm_kernel<0>, cudaFuncAttributeMaxDynamicSharedMemorySize, SMEM_BYTES);
    cudaFuncSetAttribute(gemm_kernel<1>, cudaFuncAttributeMaxDynamicSharedMemorySize, SMEM_BYTES);

    init_kernel<<<1024, 256>>>(b_d, x, Wmih, Wmhh, Wih, Whh);

    for (int t = 0; t < T_; t++) {
        gemm_kernel<0><<<dim3(N1 / 64, 4), 256, SMEM_BYTES>>>(t);
        epi1_kernel<<<BH / 256, 256>>>(bmih, bmhh, t);
        gemm_kernel<1><<<dim3(N2 / 64, 4), 256, SMEM_BYTES>>>(t);
        epi2_kernel<<<BH / 256, 256>>>(bih, bhh, len, t);
    }

    head_kernel<<<64, 128>>>(Wout, bout, out);
}

// round 7
// speedup vs baseline: 4.1655x; 1.2648x over previous
#include <cuda_runtime.h>
#include <cuda_bf16.h>
#include <cstdint>

typedef uint32_t u32;
typedef uint64_t u64;
typedef unsigned short u16;

// ---------------------------------------------------------------------------
// MLSTMFixD, round 7:
//  - bf16 3-term split GEMMs (fp32 accurate) via mma.sync (legacy path, sm_103-safe)
//  - x@Wmih precomputed for ALL t as one big GEMM (off the sequential path)
//  - per-step GEMMs: 2-way K-split, 3-stage cp.async, 1 sync/chunk, 2 CTAs/SM
// ---------------------------------------------------------------------------

constexpr int T_   = 128;
constexpr int B_   = 256;
constexpr int I_   = 512;
constexpr int H_   = 512;
constexpr int O_   = 5;
constexpr int KLAG = 32;
constexpr int BH   = B_ * H_;
constexpr int N1   = 3 * H_;   // 1536
constexpr int N2   = 4 * H_;   // 2048

// smem: 3 stages x (Ahi|Alo|Bhi|Blo, 8KB each) = 96KB
constexpr int SMEM_BYTES = 3 * 32768;

// ------------------------- device scratch (static) -------------------------
__device__ __align__(16) u16 g_xhi[T_ * B_ * I_];          // x split hi
__device__ __align__(16) u16 g_xlo[T_ * B_ * I_];          // x split lo
__device__ __align__(16) u16 g_WxHi[N1 * 512], g_WxLo[N1 * 512];   // Wmih
__device__ __align__(16) u16 g_W1Hi[N1 * 512], g_W1Lo[N1 * 512];   // Wmhh
__device__ __align__(16) u16 g_W2Hi[N2 * 1024], g_W2Lo[N2 * 1024]; // [Wih|Whh]
__device__ __align__(16) u16 g_h1hi[BH], g_h1lo[BH];
__device__ __align__(16) u16 g_h2hi[BH], g_h2lo[BH];
__device__ float g_c2[BH];
__device__ float g_sel[BH];
__device__ float g_hist[KLAG][BH];          // circular by (t & 31)
__device__ float g_wd[KLAG][H_];
__device__ float g_XW[(size_t)T_ * B_ * N1];                // 201MB: x @ Wmih^T, all t
__device__ float g_G1[2][B_ * N1];          // K-split partials, GEMM1
__device__ float g_G2[2][B_ * N2];          // K-split partials, GEMM2

// ------------------------------- helpers ------------------------------------
__device__ __forceinline__ u32 smem_u32(const void* p) {
    u32 a;
    asm("{ .reg .u64 t; cvta.to.shared.u64 t, %1; cvt.u32.u64 %0, t; }" : "=r"(a) : "l"(p));
    return a;
}
__device__ __forceinline__ void cpasync16(u32 dst, const void* src) {
    asm volatile("cp.async.cg.shared.global [%0], [%1], 16;" :: "r"(dst), "l"(src));
}
#define CP_COMMIT() asm volatile("cp.async.commit_group;" ::: "memory")
#define CP_WAIT(n)  asm volatile("cp.async.wait_group %0;" :: "n"(n) : "memory")

#define LDSM4(r, addr) asm volatile(                                           \
    "ldmatrix.sync.aligned.m8n8.x4.shared.b16 {%0,%1,%2,%3}, [%4];"            \
    : "=r"((r)[0]), "=r"((r)[1]), "=r"((r)[2]), "=r"((r)[3]) : "r"(addr))

#define MMA(d, a, b0, b1) asm volatile(                                        \
    "mma.sync.aligned.m16n8k16.row.col.f32.bf16.bf16.f32 "                     \
    "{%0,%1,%2,%3}, {%4,%5,%6,%7}, {%8,%9}, {%0,%1,%2,%3};"                    \
    : "+f"((d)[0]), "+f"((d)[1]), "+f"((d)[2]), "+f"((d)[3])                   \
    : "r"((a)[0]), "r"((a)[1]), "r"((a)[2]), "r"((a)[3]), "r"(b0), "r"(b1))

__device__ __forceinline__ u16 bf16bits(__nv_bfloat16 v) {
    __nv_bfloat16_raw r = *reinterpret_cast<__nv_bfloat16_raw*>(&v);
    return r.x;
}
__device__ __forceinline__ void split1(float a, u16& h, u16& l) {
    __nv_bfloat16 bh = __float2bfloat16_rn(a);
    float r = a - __bfloat162float(bh);
    __nv_bfloat16 bl = __float2bfloat16_rn(r);
    h = bf16bits(bh);
    l = bf16bits(bl);
}
__device__ __forceinline__ void split4(float4 v, u32& h01, u32& h23, u32& l01, u32& l23) {
    u16 h0, l0, h1, l1, h2, l2, h3, l3;
    split1(v.x, h0, l0); split1(v.y, h1, l1);
    split1(v.z, h2, l2); split1(v.w, h3, l3);
    h01 = (u32)h0 | ((u32)h1 << 16);  h23 = (u32)h2 | ((u32)h3 << 16);
    l01 = (u32)l0 | ((u32)l1 << 16);  l23 = (u32)l2 | ((u32)l3 << 16);
}
__device__ __forceinline__ float sigf(float x) { return 1.0f / (1.0f + expf(-x)); }

// ------------------------------- init ---------------------------------------
__global__ __launch_bounds__(256) void init_kernel(
    const float* __restrict__ b_d,  const float* __restrict__ x,
    const float* __restrict__ Wmih, const float* __restrict__ Wmhh,
    const float* __restrict__ Wih,  const float* __restrict__ Whh)
{
    const int tid = blockIdx.x * blockDim.x + threadIdx.x;
    const int tot = gridDim.x * blockDim.x;

    // x split (float4 groups)
    const int ngx = T_ * B_ * I_ / 4;
    for (int i = tid; i < ngx; i += tot) {
        float4 v = reinterpret_cast<const float4*>(x)[i];
        u32 h01, h23, l01, l23;
        split4(v, h01, h23, l01, l23);
        reinterpret_cast<uint2*>(g_xhi)[i] = make_uint2(h01, h23);
        reinterpret_cast<uint2*>(g_xlo)[i] = make_uint2(l01, l23);
    }

    // weight splits
    const int ngWx = N1 * 512 / 4;
    for (int i = tid; i < ngWx; i += tot) {
        float4 v = reinterpret_cast<const float4*>(Wmih)[i];
        u32 h01, h23, l01, l23; split4(v, h01, h23, l01, l23);
        reinterpret_cast<uint2*>(g_WxHi)[i] = make_uint2(h01, h23);
        reinterpret_cast<uint2*>(g_WxLo)[i] = make_uint2(l01, l23);
    }
    for (int i = tid; i < ngWx; i += tot) {
        float4 v = reinterpret_cast<const float4*>(Wmhh)[i];
        u32 h01, h23, l01, l23; split4(v, h01, h23, l01, l23);
        reinterpret_cast<uint2*>(g_W1Hi)[i] = make_uint2(h01, h23);
        reinterpret_cast<uint2*>(g_W1Lo)[i] = make_uint2(l01, l23);
    }
    const int ngW2 = N2 * 1024 / 4;
    for (int i = tid; i < ngW2; i += tot) {
        int e = i * 4;
        int n = e >> 10, k = e & 1023;
        const float* src = (k < 512) ? (Wih + (size_t)n * 512 + k)
                                     : (Whh + (size_t)n * 512 + (k - 512));
        float4 v = *reinterpret_cast<const float4*>(src);
        u32 h01, h23, l01, l23; split4(v, h01, h23, l01, l23);
        reinterpret_cast<uint2*>(g_W2Hi)[i] = make_uint2(h01, h23);
        reinterpret_cast<uint2*>(g_W2Lo)[i] = make_uint2(l01, l23);
    }

    // zero state
    float4 z4 = make_float4(0.f, 0.f, 0.f, 0.f);
    for (int i = tid; i < KLAG * BH / 4; i += tot)
        reinterpret_cast<float4*>(&g_hist[0][0])[i] = z4;
    for (int i = tid; i < BH / 4; i += tot) {
        reinterpret_cast<float4*>(g_c2)[i]  = z4;
        reinterpret_cast<float4*>(g_sel)[i] = z4;
        reinterpret_cast<uint2*>(g_h1hi)[i] = make_uint2(0u, 0u);
        reinterpret_cast<uint2*>(g_h1lo)[i] = make_uint2(0u, 0u);
        reinterpret_cast<uint2*>(g_h2hi)[i] = make_uint2(0u, 0u);
        reinterpret_cast<uint2*>(g_h2lo)[i] = make_uint2(0u, 0u);
    }

    // frac-diff coefficients
    if (tid < H_) {
        float d = 0.5f * (1.0f / (1.0f + expf(-b_d[tid])));
        float c = 1.0f;
        for (int j = 1; j <= KLAG; j++) {
            c *= ((float)(j - 1) - d) / (float)j;
            g_wd[j - 1][tid] = c;
        }
    }
}

// ------------------------------- GEMM ---------------------------------------
// SET=0: XW[32768,1536] = x @ Wmih^T         grid (24, 512)     K=512, 8 chunks
// SET=1: G1[kz][256,1536] = h1 @ Wmhh^T      grid (24, 4, 2)    K=256/CTA, 4 chunks
// SET=2: G2[kz][256,2048] = [h1n|h2] @ W2^T  grid (32, 4, 2)    K=512/CTA, 8 chunks
// CTA 64x64, 8 warps (warp tile 32x16), 3-stage cp.async, 1 sync per chunk.
template <int SET>
__global__ __launch_bounds__(256, 2) void gemm_kernel(int t)
{
    constexpr int NC  = (SET == 1) ? 4 : 8;
    constexpr int ldB = (SET == 2) ? 1024 : 512;
    constexpr int ldG = (SET == 2) ? N2 : N1;

    extern __shared__ __align__(128) char smem[];
    const u32 sb  = smem_u32(smem);
    const int tid = threadIdx.x;
    const int wid = tid >> 5, lane = tid & 31;
    const int bn  = blockIdx.x * 64;
    const int bm  = blockIdx.y * 64;
    const int kz  = (SET == 0) ? 0 : blockIdx.z;
    const int kbase = (SET == 0) ? 0 : ((SET == 1) ? kz * 256 : kz * 512);

    const u16* __restrict__ A0hi = (SET == 0) ? g_xhi : g_h1hi;
    const u16* __restrict__ A0lo = (SET == 0) ? g_xlo : g_h1lo;
    const u16* __restrict__ BHi  = (SET == 0) ? g_WxHi : ((SET == 1) ? g_W1Hi : g_W2Hi);
    const u16* __restrict__ BLo  = (SET == 0) ? g_WxLo : ((SET == 1) ? g_W1Lo : g_W2Lo);
    float* __restrict__ G =
        (SET == 0) ? g_XW : ((SET == 1) ? g_G1[kz] : g_G2[kz]);

    // loader: per chunk each thread moves 8x 16B units (2 per 8KB tile)
    const int lr  = tid >> 3;          // unit row for j=0 (0..31)
    const int lcu = tid & 7;           // unit col 0..7
    auto load_chunk = [&](int c, int stage) {
        const int k0 = kbase + c * 64;                 // global k in [0, 512|1024)
        const u16* ah; const u16* al;
        if (SET == 2 && k0 >= 512) { ah = g_h2hi + (k0 - 512); al = g_h2lo + (k0 - 512); }
        else                       { ah = A0hi + k0;           al = A0lo + k0;           }
        const u32 base = sb + stage * 32768;
#pragma unroll
        for (int j = 0; j < 2; j++) {
            const int r = lr + j * 32;
            const u32 so = (u32)(r * 128 + ((lcu ^ (r & 7)) << 4));
            const size_t ao = (size_t)(bm + r) * 512 + lcu * 8;
            const size_t bo = (size_t)(bn + r) * ldB + k0 + lcu * 8;
            cpasync16(base + so,         ah  + ao);
            cpasync16(base + 8192 + so,  al  + ao);
            cpasync16(base + 16384 + so, BHi + bo);
            cpasync16(base + 24576 + so, BLo + bo);
        }
    };

    // fragment addressing
    const int warp_m = wid & 1;
    const int warp_n = wid >> 1;
    const int arow   = warp_m * 32 + (lane & 15);
    const int akh    = lane >> 4;
    const int brow   = warp_n * 16 + (lane & 7) + ((lane >> 4) << 3);
    const int bkh    = (lane >> 3) & 1;
    const u32 aoff0  = (u32)(arow * 128);
    const u32 aoff1  = (u32)((arow + 16) * 128);
    const int asw    = arow & 7;
    const u32 boff   = (u32)(brow * 128);
    const int bsw    = brow & 7;

    float acc[2][2][4] = {};

    load_chunk(0, 0); CP_COMMIT();
    load_chunk(1, 1); CP_COMMIT();

    for (int c = 0; c < NC; c++) {
        if (c + 1 < NC) { CP_WAIT(1); } else { CP_WAIT(0); }
        __syncthreads();
        if (c + 2 < NC) { load_chunk(c + 2, (c + 2) % 3); CP_COMMIT(); }

        const u32 Ah = sb + (c % 3) * 32768;
        const u32 Al = Ah + 8192;
        const u32 Bh = Ah + 16384;
        const u32 Bl = Ah + 24576;

#pragma unroll
        for (int kk = 0; kk < 4; kk++) {
            const u32 sa  = (((u32)(kk * 2 + akh) ^ (u32)asw) << 4);
            const u32 sbo = (((u32)(kk * 2 + bkh) ^ (u32)bsw) << 4);

            u32 ah0[4], ah1[4], al0[4], al1[4], bh[4], bl[4];
            LDSM4(ah0, Ah + aoff0 + sa);
            LDSM4(ah1, Ah + aoff1 + sa);
            LDSM4(al0, Al + aoff0 + sa);
            LDSM4(al1, Al + aoff1 + sa);
            LDSM4(bh,  Bh + boff + sbo);
            LDSM4(bl,  Bl + boff + sbo);

#pragma unroll
            for (int nt = 0; nt < 2; nt++) {
                MMA(acc[0][nt], ah0, bh[2 * nt], bh[2 * nt + 1]);
                MMA(acc[1][nt], ah1, bh[2 * nt], bh[2 * nt + 1]);
                MMA(acc[0][nt], ah0, bl[2 * nt], bl[2 * nt + 1]);
                MMA(acc[1][nt], ah1, bl[2 * nt], bl[2 * nt + 1]);
                MMA(acc[0][nt], al0, bh[2 * nt], bh[2 * nt + 1]);
                MMA(acc[1][nt], al1, bh[2 * nt], bh[2 * nt + 1]);
            }
        }
    }

    // epilogue: fp32 accumulators -> G
#pragma unroll
    for (int mt = 0; mt < 2; mt++) {
#pragma unroll
        for (int nt = 0; nt < 2; nt++) {
            const int gm = bm + warp_m * 32 + mt * 16 + (lane >> 2);
            const int gn = bn + warp_n * 16 + nt * 8 + 2 * (lane & 3);
            *reinterpret_cast<float2*>(&G[(size_t)gm * ldG + gn]) =
                make_float2(acc[mt][nt][0], acc[mt][nt][1]);
            *reinterpret_cast<float2*>(&G[(size_t)(gm + 8) * ldG + gn]) =
                make_float2(acc[mt][nt][2], acc[mt][nt][3]);
        }
    }
}

// --------------------- epilogue 1: mLSTM gates + frac filter -----------------
__global__ __launch_bounds__(256) void epi1_kernel(
    const float* __restrict__ bmih, const float* __restrict__ bmhh, int t)
{
    const int idx = blockIdx.x * blockDim.x + threadIdx.x;
    const int b = idx >> 9, hc = idx & 511;
    const float* __restrict__ Ga = g_G1[0] + (size_t)b * N1;
    const float* __restrict__ Gb = g_G1[1] + (size_t)b * N1;
    const float* __restrict__ Gx = g_XW + ((size_t)t * B_ + b) * N1;

    float vi = sigf (Ga[hc]        + Gb[hc]        + Gx[hc]        + bmih[hc]        + bmhh[hc]);
    float vo = sigf (Ga[512 + hc]  + Gb[512 + hc]  + Gx[512 + hc]  + bmih[512 + hc]  + bmhh[512 + hc]);
    float vg = tanhf(Ga[1024 + hc] + Gb[1024 + hc] + Gx[1024 + hc] + bmih[1024 + hc] + bmhh[1024 + hc]);

    float fs = 0.0f;
#pragma unroll
    for (int j = 1; j <= KLAG; j++)
        fs = fmaf(g_wd[j - 1][hc], g_hist[(t - j) & (KLAG - 1)][idx], fs);

    float c1 = vi * vg - fs;
    g_hist[t & (KLAG - 1)][idx] = c1;
    float h1n = vo * tanhf(c1);
    split1(h1n, g_h1hi[idx], g_h1lo[idx]);
}

// --------------------- epilogue 2: LSTM cell + gather ------------------------
__global__ __launch_bounds__(256) void epi2_kernel(
    const float* __restrict__ bih, const float* __restrict__ bhh,
    const int* __restrict__ length, int t)
{
    const int idx = blockIdx.x * blockDim.x + threadIdx.x;
    const int b = idx >> 9, hc = idx & 511;
    const float* __restrict__ Ga = g_G2[0] + (size_t)b * N2;
    const float* __restrict__ Gb = g_G2[1] + (size_t)b * N2;

    float xi = sigf (Ga[hc]        + Gb[hc]        + bih[hc]        + bhh[hc]);
    float xf = sigf (Ga[512 + hc]  + Gb[512 + hc]  + bih[512 + hc]  + bhh[512 + hc]);
    float xg = tanhf(Ga[1024 + hc] + Gb[1024 + hc] + bih[1024 + hc] + bhh[1024 + hc]);
    float xo = sigf (Ga[1536 + hc] + Gb[1536 + hc] + bih[1536 + hc] + bhh[1536 + hc]);

    float cn = xf * g_c2[idx] + xi * xg;
    g_c2[idx] = cn;
    float hv = tanhf(xo * tanhf(cn));
    split1(hv, g_h2hi[idx], g_h2lo[idx]);
    if (length[b] == t) g_sel[idx] = hv;
}

// ------------------------------- head ---------------------------------------
__global__ __launch_bounds__(128) void head_kernel(
    const float* __restrict__ Wout, const float* __restrict__ bout,
    float* __restrict__ out)
{
    const int warp = (blockIdx.x * blockDim.x + threadIdx.x) >> 5;
    const int lane = threadIdx.x & 31;
    if (warp >= B_) return;

    float p[O_] = {0.f, 0.f, 0.f, 0.f, 0.f};
    for (int h = lane; h < H_; h += 32) {
        float s = g_sel[warp * H_ + h];
#pragma unroll
        for (int o = 0; o < O_; o++) p[o] = fmaf(s, Wout[o * H_ + h], p[o]);
    }
#pragma unroll
    for (int o = 0; o < O_; o++)
#pragma unroll
        for (int off = 16; off > 0; off >>= 1)
            p[o] += __shfl_xor_sync(0xffffffffu, p[o], off);

    if (lane == 0) {
        float l[O_], m = -1e30f;
#pragma unroll
        for (int o = 0; o < O_; o++) { l[o] = p[o] + bout[o]; m = fmaxf(m, l[o]); }
        float s = 0.0f;
#pragma unroll
        for (int o = 0; o < O_; o++) s += expf(l[o] - m);
        float ls = logf(s);
#pragma unroll
        for (int o = 0; o < O_; o++) out[warp * O_ + o] = l[o] - m - ls;
    }
}

// ----------------------------- launcher -------------------------------------
extern "C" void kernel_launch(void* const* d_in, const int* in_sizes, int n_in,
                              void* d_out, int out_size)
{
    const float* x    = (const float*)d_in[0];   // (T,B,I)
    const int*   len  = (const int*)  d_in[1];   // (B,)
    const float* b_d  = (const float*)d_in[2];   // (1,H)
    const float* Wmih = (const float*)d_in[3];   // (3H,I)
    const float* Wmhh = (const float*)d_in[4];   // (3H,H)
    const float* bmih = (const float*)d_in[5];   // (3H,)
    const float* bmhh = (const float*)d_in[6];   // (3H,)
    const float* Wih  = (const float*)d_in[7];   // (4H,H)
    const float* Whh  = (const float*)d_in[8];   // (4H,H)
    const float* bih  = (const float*)d_in[9];   // (4H,)
    const float* bhh  = (const float*)d_in[10];  // (4H,)
    const float* Wout = (const float*)d_in[11];  // (O,H)
    const float* bout = (const float*)d_in[12];  // (O,)
    float* out = (float*)d_out;                  // (B,O)

    cudaFuncSetAttribute(gemm_kernel<0>, cudaFuncAttributeMaxDynamicSharedMemorySize, SMEM_BYTES);
    cudaFuncSetAttribute(gemm_kernel<1>, cudaFuncAttributeMaxDynamicSharedMemorySize, SMEM_BYTES);
    cudaFuncSetAttribute(gemm_kernel<2>, cudaFuncAttributeMaxDynamicSharedMemorySize, SMEM_BYTES);

    init_kernel<<<1024, 256>>>(b_d, x, Wmih, Wmhh, Wih, Whh);

    // hoisted input projection: one big GEMM over all timesteps
    gemm_kernel<0><<<dim3(N1 / 64, (T_ * B_) / 64), 256, SMEM_BYTES>>>(0);

    for (int t = 0; t < T_; t++) {
        gemm_kernel<1><<<dim3(N1 / 64, 4, 2), 256, SMEM_BYTES>>>(t);
        epi1_kernel<<<BH / 256, 256>>>(bmih, bmhh, t);
        gemm_kernel<2><<<dim3(N2 / 64, 4, 2), 256, SMEM_BYTES>>>(t);
        epi2_kernel<<<BH / 256, 256>>>(bih, bhh, len, t);
    }

    head_kernel<<<64, 128>>>(Wout, bout, out);
}